// round 13
// baseline (speedup 1.0000x reference)
#include <cuda_runtime.h>
#include <stdint.h>

// BurgerDissipativeLossOperator
//   du[i]  = (u1[i]*A[i] - B[i]) / max(cnt[i],1)   A=Σ 1/len, B=Σ u1[src]/len
//   d2u[i] = (du[i]*A[i] - C[i]) / max(cnt[i],1)   C=Σ du[src]/len
//   loss   = ((u0-u1)/dt + du*u1 - MU*d2u) * mask
//
// V = Σ (256 + 1/len) = 256*cnt + A packs cnt+A into one float ->
// pass 1 is one red.global.add.v2.f32 {V,B} per edge (8B RMW, 1 sector).
// g_u1 removed: edge1 gathers x_t1[2s] directly (same sector count, 32MB
// footprint still L2-resident); k_init is a pure zero-fill (-48MB).
// Rules (R3/R10): gather arrays read-only per pass; RMW arrays separate.

#define N_NODES 4000000
#define N_EDGES 8000000
#define INV_DT  100.0f
#define MU      0.01f
#define K_PACK  256.0f
#define INV_K   0.00390625f   // 1/256

__device__ float2 g_acc[N_NODES];   // {V = 256*cnt + A, B}
__device__ float  g_C[N_NODES];     // Σ du[src]/len
__device__ float  g_du[N_NODES];    // written by k_du, gathered by k_edge2

// unpack V and compute du (fast reciprocal)
__device__ __forceinline__ float node_du(float V, float B, float u1,
                                         float& A, float& rc) {
    float k = floorf(V * INV_K);          // cnt
    A  = V - K_PACK * k;
    rc = __fdividef(1.0f, fmaxf(k, 1.0f));
    return (u1 * A - B) * rc;
}

// ---------------------------------------------------------------------------
// init (4 nodes/thread): pure zero-fill of accumulators
__global__ void __launch_bounds__(256) k_init() {
    int t = blockIdx.x * blockDim.x + threadIdx.x;
    if (t >= N_NODES / 4) return;
    float4 z = make_float4(0.f, 0.f, 0.f, 0.f);
    ((float4*)g_acc)[t * 2 + 0] = z;
    ((float4*)g_acc)[t * 2 + 1] = z;
    ((float4*)g_C)[t] = z;
}

// pass 1 (4 edges/thread): red.v2 {V += 256 + 1/len, B += u1[s]/len}
__global__ void __launch_bounds__(256) k_edge1(const int4* __restrict__ ei_s,
                                               const int4* __restrict__ ei_d,
                                               const float4* __restrict__ attr,
                                               const float* __restrict__ x_t1) {
    int t = blockIdx.x * blockDim.x + threadIdx.x;
    if (t >= N_EDGES / 4) return;
    int4   s4 = __ldcs(&ei_s[t]);
    int4   d4 = __ldcs(&ei_d[t]);
    float4 l4 = __ldcs(&attr[t]);

    float u0 = __ldg(&x_t1[2 * s4.x]);
    float u1 = __ldg(&x_t1[2 * s4.y]);
    float u2 = __ldg(&x_t1[2 * s4.z]);
    float u3 = __ldg(&x_t1[2 * s4.w]);

    float r0 = __fdividef(1.0f, l4.x);
    float r1 = __fdividef(1.0f, l4.y);
    float r2 = __fdividef(1.0f, l4.z);
    float r3 = __fdividef(1.0f, l4.w);

    asm volatile("red.global.add.v2.f32 [%0], {%1, %2};"
                 :: "l"(&g_acc[d4.x]), "f"(K_PACK + r0), "f"(u0 * r0) : "memory");
    asm volatile("red.global.add.v2.f32 [%0], {%1, %2};"
                 :: "l"(&g_acc[d4.y]), "f"(K_PACK + r1), "f"(u1 * r1) : "memory");
    asm volatile("red.global.add.v2.f32 [%0], {%1, %2};"
                 :: "l"(&g_acc[d4.z]), "f"(K_PACK + r2), "f"(u2 * r2) : "memory");
    asm volatile("red.global.add.v2.f32 [%0], {%1, %2};"
                 :: "l"(&g_acc[d4.w]), "f"(K_PACK + r3), "f"(u3 * r3) : "memory");
}

// node pass (4 nodes/thread): du = (u1*A - B) / max(cnt,1)
__global__ void __launch_bounds__(256) k_du(const float4* __restrict__ x_t1) {
    int t = blockIdx.x * blockDim.x + threadIdx.x;
    if (t >= N_NODES / 4) return;
    float4 xa = __ldg(&x_t1[t * 2 + 0]);   // u1[4t],v,u1[4t+1],v
    float4 xb = __ldg(&x_t1[t * 2 + 1]);   // u1[4t+2],v,u1[4t+3],v
    float4 p0 = ((const float4*)g_acc)[t * 2 + 0];  // {V0,B0,V1,B1}
    float4 p1 = ((const float4*)g_acc)[t * 2 + 1];  // {V2,B2,V3,B3}
    float A, rc;
    float4 du;
    du.x = node_du(p0.x, p0.y, xa.x, A, rc);
    du.y = node_du(p0.z, p0.w, xa.z, A, rc);
    du.z = node_du(p1.x, p1.y, xb.x, A, rc);
    du.w = node_du(p1.z, p1.w, xb.z, A, rc);
    ((float4*)g_du)[t] = du;
}

// pass 2 (4 edges/thread): C[d] += du[s]/len
__global__ void __launch_bounds__(256) k_edge2(const int4* __restrict__ ei_s,
                                               const int4* __restrict__ ei_d,
                                               const float4* __restrict__ attr) {
    int t = blockIdx.x * blockDim.x + threadIdx.x;
    if (t >= N_EDGES / 4) return;
    int4   s4 = __ldcs(&ei_s[t]);
    int4   d4 = __ldcs(&ei_d[t]);
    float4 l4 = __ldcs(&attr[t]);

    float d0 = __ldg(&g_du[s4.x]);
    float d1 = __ldg(&g_du[s4.y]);
    float d2 = __ldg(&g_du[s4.z]);
    float d3 = __ldg(&g_du[s4.w]);

    atomicAdd(&g_C[d4.x], d0 * __fdividef(1.0f, l4.x));
    atomicAdd(&g_C[d4.y], d1 * __fdividef(1.0f, l4.y));
    atomicAdd(&g_C[d4.z], d2 * __fdividef(1.0f, l4.z));
    atomicAdd(&g_C[d4.w], d3 * __fdividef(1.0f, l4.w));
}

// epilogue (4 nodes/thread): recompute du from {V,B,u1}
__device__ __forceinline__ float node_loss(float V, float B, float C,
                                           float u0, float u1, float m) {
    float A, rc;
    float du  = node_du(V, B, u1, A, rc);
    float d2u = (du * A - C) * rc;
    return ((u0 - u1) * INV_DT + du * u1 - MU * d2u) * m;
}

__global__ void __launch_bounds__(256) k_final(const float4* __restrict__ x_t,
                                               const float4* __restrict__ x_t1,
                                               const float4* __restrict__ mask,
                                               float4* __restrict__ out) {
    int t = blockIdx.x * blockDim.x + threadIdx.x;
    if (t >= N_NODES / 4) return;
    float4 p0 = ((const float4*)g_acc)[t * 2 + 0];
    float4 p1 = ((const float4*)g_acc)[t * 2 + 1];
    float4 C  = ((const float4*)g_C)[t];
    float4 ya = __ldg(&x_t1[t * 2 + 0]);     // likely L2-resident from k_du
    float4 yb = __ldg(&x_t1[t * 2 + 1]);
    float4 xa = __ldcs(&x_t[t * 2 + 0]);
    float4 xb = __ldcs(&x_t[t * 2 + 1]);
    float4 m  = __ldcs(&mask[t]);

    float4 o;
    o.x = node_loss(p0.x, p0.y, C.x, xa.x, ya.x, m.x);
    o.y = node_loss(p0.z, p0.w, C.y, xa.z, ya.z, m.y);
    o.z = node_loss(p1.x, p1.y, C.z, xb.x, yb.x, m.z);
    o.w = node_loss(p1.z, p1.w, C.w, xb.z, yb.z, m.w);
    __stcs(&out[t], o);
}

// ---------------------------------------------------------------------------
extern "C" void kernel_launch(void* const* d_in, const int* in_sizes, int n_in,
                              void* d_out, int out_size) {
    const float4* x_t   = (const float4*)d_in[0];
    const float*  x_t1  = (const float*)d_in[1];
    const float4* x_t1v = (const float4*)d_in[1];
    const int*    ei    = (const int*)d_in[2];
    const float4* attr  = (const float4*)d_in[3];
    const float4* mask  = (const float4*)d_in[4];
    float4*       out   = (float4*)d_out;

    const int4* ei_s = (const int4*)ei;
    const int4* ei_d = (const int4*)(ei + N_EDGES);

    const int TB = 256;
    const int gn = (N_NODES / 4 + TB - 1) / TB;
    const int ge = (N_EDGES / 4 + TB - 1) / TB;

    k_init <<<gn, TB>>>();
    k_edge1<<<ge, TB>>>(ei_s, ei_d, attr, x_t1);
    k_du   <<<gn, TB>>>(x_t1v);
    k_edge2<<<ge, TB>>>(ei_s, ei_d, attr);
    k_final<<<gn, TB>>>(x_t, x_t1v, mask, out);
}